// round 1
// baseline (speedup 1.0000x reference)
#include <cuda_runtime.h>

#define TS   32
#define HALO 6
#define LW   (TS + 2*HALO)   // 44

#define N_PIX   87040
#define BATCH   128

// unnormalized 1-D Gaussian taps exp(-k^2/18), sigma=3, radius 6
__device__ __constant__ float c_taps[7] = {
    1.0f,
    0.94595947f,   // exp(-1/18)
    0.80073740f,   // exp(-4/18)
    0.60653066f,   // exp(-9/18)
    0.41111229f,   // exp(-16/18)
    0.24935220f,   // exp(-25/18)
    0.13533528f    // exp(-36/18)
};

__global__ __launch_bounds__(256, 8)
void lln_kernel(const float* __restrict__ x, float* __restrict__ out)
{
    // ---- map blockIdx.x (0..84) to (level, tile-within-level) ----
    int tile = blockIdx.x;
    int b    = blockIdx.y;

    int lvl, tloc;
    if      (tile < 64) { lvl = 0; tloc = tile;      }
    else if (tile < 80) { lvl = 1; tloc = tile - 64; }
    else if (tile < 84) { lvl = 2; tloc = tile - 80; }
    else                { lvl = 3; tloc = 0;         }

    const int dims[4] = {256, 128, 64, 32};
    const int offs[4] = {0, 65536, 81920, 86016};
    const int tpr [4] = {8, 4, 2, 1};

    const int w   = dims[lvl];
    const int h   = w;
    const int off = offs[lvl];

    const int tx0 = (tloc % tpr[lvl]) * TS;
    const int ty0 = (tloc / tpr[lvl]) * TS;

    const float* __restrict__ base = x   + ((size_t)b * N_PIX + off) * 3;
    float*       __restrict__ obase = out + ((size_t)b * N_PIX + off) * 3;

    __shared__ float s_lum[LW][LW];   // 44x44 luminance incl. halo
    __shared__ float s_h  [LW][TS];   // horizontal-blurred, halo rows kept

    const int tid = threadIdx.x;

    // ---- phase 1: load RGB, reduce to luminance, zero-pad outside image ----
    for (int i = tid; i < LW * LW; i += 256) {
        int r  = i / LW;
        int c  = i - r * LW;
        int gy = ty0 - HALO + r;
        int gx = tx0 - HALO + c;
        float v = 0.0f;
        if (gy >= 0 && gy < h && gx >= 0 && gx < w) {
            const float* p = base + ((size_t)gy * w + gx) * 3;
            v = 0.2989f * p[0] + 0.587f * p[1] + 0.114f * p[2];
        }
        s_lum[r][c] = v;
    }
    __syncthreads();

    // ---- phase 2: horizontal 13-tap blur (all 44 rows, 32 output cols) ----
    for (int i = tid; i < LW * TS; i += 256) {
        int r = i / TS;
        int c = i - r * TS;
        float acc = c_taps[0] * s_lum[r][c + HALO];
#pragma unroll
        for (int k = 1; k <= 6; k++)
            acc += c_taps[k] * (s_lum[r][c + HALO - k] + s_lum[r][c + HALO + k]);
        s_h[r][c] = acc;
    }
    __syncthreads();

    // ---- phase 3: vertical blur + analytic dens + divide + store ----
    for (int i = tid; i < TS * TS; i += 256) {
        int r  = i / TS;
        int c  = i - r * TS;
        int gy = ty0 + r;
        int gx = tx0 + c;

        float acc = c_taps[0] * s_h[r + HALO][c];
#pragma unroll
        for (int k = 1; k <= 6; k++)
            acc += c_taps[k] * (s_h[r + HALO - k][c] + s_h[r + HALO + k][c]);

        // dens = W * Sy(gy) * Sx(gx) ; clipped 1-D tap sums (zero padding)
        float sy = c_taps[0], sx = c_taps[0];
#pragma unroll
        for (int k = 1; k <= 6; k++) {
            sy += (gy - k >= 0 ? c_taps[k] : 0.0f) + (gy + k < h ? c_taps[k] : 0.0f);
            sx += (gx - k >= 0 ? c_taps[k] : 0.0f) + (gx + k < w ? c_taps[k] : 0.0f);
        }
        float dens = 0.9999f * sy * sx;

        float inv = 1.0f / (acc / dens + 1e-3f);

        size_t pidx = ((size_t)gy * w + gx) * 3;
        const float* p = base  + pidx;
        float*       q = obase + pidx;
        q[0] = p[0] * inv;
        q[1] = p[1] * inv;
        q[2] = p[2] * inv;
    }
}

extern "C" void kernel_launch(void* const* d_in, const int* in_sizes, int n_in,
                              void* d_out, int out_size)
{
    const float* x = (const float*)d_in[0];
    float* out     = (float*)d_out;
    dim3 grid(85, BATCH);
    lln_kernel<<<grid, 256>>>(x, out);
}

// round 2
// speedup vs baseline: 1.2222x; 1.2222x over previous
#include <cuda_runtime.h>

#define TS   32
#define HALO 6
#define LW   (TS + 2*HALO)   // 44

#define N_PIX   87040
#define BATCH   128

__global__ __launch_bounds__(256, 6)
void lln_kernel(const float* __restrict__ x, float* __restrict__ out)
{
    // unnormalized 1-D Gaussian taps exp(-k^2/18), sigma=3, radius 6 (literals -> FFMA-imm)
    const float T0 = 1.0f;
    const float T1 = 0.94595947f;
    const float T2 = 0.80073740f;
    const float T3 = 0.60653066f;
    const float T4 = 0.41111229f;
    const float T5 = 0.24935220f;
    const float T6 = 0.13533528f;

    // ---- map blockIdx.x (0..84) to (level, tile-within-level) ----
    int tile = blockIdx.x;
    int b    = blockIdx.y;

    int lvl, tloc;
    if      (tile < 64) { lvl = 0; tloc = tile;      }
    else if (tile < 80) { lvl = 1; tloc = tile - 64; }
    else if (tile < 84) { lvl = 2; tloc = tile - 80; }
    else                { lvl = 3; tloc = 0;         }

    const int dims[4] = {256, 128, 64, 32};
    const int offs[4] = {0, 65536, 81920, 86016};
    const int tpr [4] = {8, 4, 2, 1};

    const int w   = dims[lvl];
    const int h   = w;
    const int off = offs[lvl];

    const int tx0 = (tloc % tpr[lvl]) * TS;
    const int ty0 = (tloc / tpr[lvl]) * TS;

    const float* __restrict__ base  = x   + ((size_t)b * N_PIX + off) * 3;
    float*       __restrict__ obase = out + ((size_t)b * N_PIX + off) * 3;

    __shared__ __align__(16) float s_lum[LW][LW];   // 44x44 luminance incl. halo
    __shared__ __align__(16) float s_h  [LW][TS];   // horizontally blurred (44 rows x 32 cols)
    __shared__ float s_sx[TS];                      // clipped horizontal tap sums per output col
    __shared__ float s_sy[TS];                      // clipped vertical tap sums per output row

    const int tid = threadIdx.x;

    // ---- dens tables: clipped 1-D tap sums (zero 'SAME' padding) ----
    if (tid < 64) {
        int p = tid & 31;
        int g = (tid < 32 ? tx0 : ty0) + p;
        float s = T0;
        s += (g >= 1 ? T1 : 0.f) + (g >= 2 ? T2 : 0.f) + (g >= 3 ? T3 : 0.f)
           + (g >= 4 ? T4 : 0.f) + (g >= 5 ? T5 : 0.f) + (g >= 6 ? T6 : 0.f);
        int d = w - 1 - g;   // w == h
        s += (d >= 1 ? T1 : 0.f) + (d >= 2 ? T2 : 0.f) + (d >= 3 ? T3 : 0.f)
           + (d >= 4 ? T4 : 0.f) + (d >= 5 ? T5 : 0.f) + (d >= 6 ? T6 : 0.f);
        if (tid < 32) s_sx[p] = s; else s_sy[p] = s;
    }

    // ---- phase 1: load RGB, reduce to luminance (fast path for interior tiles) ----
    const bool interior = (tx0 >= HALO) && (ty0 >= HALO) &&
                          (tx0 + TS + HALO <= w) && (ty0 + TS + HALO <= h);
    if (interior) {
        for (int i = tid; i < LW * LW; i += 256) {
            int r = i / LW;
            int c = i - r * LW;
            const float* p = base + ((size_t)(ty0 - HALO + r) * w + (tx0 - HALO + c)) * 3;
            s_lum[r][c] = 0.2989f * p[0] + 0.587f * p[1] + 0.114f * p[2];
        }
    } else {
        for (int i = tid; i < LW * LW; i += 256) {
            int r  = i / LW;
            int c  = i - r * LW;
            int gy = ty0 - HALO + r;
            int gx = tx0 - HALO + c;
            float v = 0.0f;
            if (gy >= 0 && gy < h && gx >= 0 && gx < w) {
                const float* p = base + ((size_t)gy * w + gx) * 3;
                v = 0.2989f * p[0] + 0.587f * p[1] + 0.114f * p[2];
            }
            s_lum[r][c] = v;
        }
    }
    __syncthreads();

    // ---- phase 2: horizontal 13-tap blur, 4 outputs/thread via LDS.128 ----
    // 44 rows x 8 col-groups = 352 tasks
    for (int i = tid; i < LW * 8; i += 256) {
        int r  = i >> 3;
        int cg = (i & 7) << 2;   // 0,4,...,28

        float4 q0 = *(const float4*)&s_lum[r][cg];
        float4 q1 = *(const float4*)&s_lum[r][cg + 4];
        float4 q2 = *(const float4*)&s_lum[r][cg + 8];
        float4 q3 = *(const float4*)&s_lum[r][cg + 12];
        float v[16] = { q0.x, q0.y, q0.z, q0.w,
                        q1.x, q1.y, q1.z, q1.w,
                        q2.x, q2.y, q2.z, q2.w,
                        q3.x, q3.y, q3.z, q3.w };

        float o[4];
#pragma unroll
        for (int j = 0; j < 4; j++) {
            o[j] = T0 *  v[j + 6]
                 + T1 * (v[j + 5] + v[j + 7])
                 + T2 * (v[j + 4] + v[j + 8])
                 + T3 * (v[j + 3] + v[j + 9])
                 + T4 * (v[j + 2] + v[j + 10])
                 + T5 * (v[j + 1] + v[j + 11])
                 + T6 * (v[j    ] + v[j + 12]);
        }
        *(float4*)&s_h[r][cg] = make_float4(o[0], o[1], o[2], o[3]);
    }
    __syncthreads();

    // ---- phase 3: vertical blur (4 rows/thread) + dens + divide + store ----
    {
        const int c  = tid & 31;
        const int r0 = (tid >> 5) << 2;   // 0,4,...,28

        float a[16];
#pragma unroll
        for (int j = 0; j < 16; j++)
            a[j] = s_h[r0 + j][c];

        const float sx = s_sx[c];
        const int   gx = tx0 + c;
        size_t idx  = ((size_t)(ty0 + r0) * w + gx) * 3;
        const size_t step = (size_t)w * 3;

#pragma unroll
        for (int j = 0; j < 4; j++) {
            float acc = T0 *  a[j + 6]
                      + T1 * (a[j + 5] + a[j + 7])
                      + T2 * (a[j + 4] + a[j + 8])
                      + T3 * (a[j + 3] + a[j + 9])
                      + T4 * (a[j + 2] + a[j + 10])
                      + T5 * (a[j + 1] + a[j + 11])
                      + T6 * (a[j    ] + a[j + 12]);

            float dens = 0.9999f * s_sy[r0 + j] * sx;
            float inv  = __fdividef(dens, acc + 1e-3f * dens);

            const float* p = base  + idx;
            float*       q = obase + idx;
            q[0] = p[0] * inv;
            q[1] = p[1] * inv;
            q[2] = p[2] * inv;
            idx += step;
        }
    }
}

extern "C" void kernel_launch(void* const* d_in, const int* in_sizes, int n_in,
                              void* d_out, int out_size)
{
    const float* x = (const float*)d_in[0];
    float* out     = (float*)d_out;
    dim3 grid(85, BATCH);
    lln_kernel<<<grid, 256>>>(x, out);
}

// round 3
// speedup vs baseline: 1.6949x; 1.3868x over previous
#include <cuda_runtime.h>

#define TS   32
#define HALO 6
#define LW   44              // TS + 2*HALO
#define N_PIX 87040

__global__ __launch_bounds__(256, 8)
void lln_kernel(const float* __restrict__ x, float* __restrict__ out)
{
    // unnormalized 1-D Gaussian taps exp(-k^2/18), sigma=3, radius 6
    const float T[7] = { 1.0f, 0.94595947f, 0.80073740f, 0.60653066f,
                         0.41111229f, 0.24935220f, 0.13533528f };

    const int tile = blockIdx.x;
    const int b    = blockIdx.y;

    int lvl, tloc;
    if      (tile < 64) { lvl = 0; tloc = tile;      }
    else if (tile < 80) { lvl = 1; tloc = tile - 64; }
    else if (tile < 84) { lvl = 2; tloc = tile - 80; }
    else                { lvl = 3; tloc = 0;         }

    const int dims[4] = {256, 128, 64, 32};
    const int offs[4] = {0, 65536, 81920, 86016};
    const int tpr [4] = {8, 4, 2, 1};

    const int w   = dims[lvl];
    const int h   = w;

    const int tx0 = (tloc % tpr[lvl]) * TS;
    const int ty0 = (tloc / tpr[lvl]) * TS;

    const int boff = b * (N_PIX * 3) + offs[lvl] * 3;
    const float* __restrict__ base  = x   + boff;
    float*       __restrict__ obase = out + boff;

    __shared__ __align__(16) float s_lum[LW][LW];   // 44x44 luminance incl. halo
    __shared__ __align__(16) float s_h  [LW][TS];   // horizontally blurred
    __shared__ float s_inv[TS][TS + 1];             // per-pixel 1/denominator (padded)
    __shared__ float s_sx[TS];
    __shared__ float s_sy[TS];

    const int tid = threadIdx.x;

    // ---- dens tables: clipped 1-D tap sums (zero 'SAME' padding) ----
    if (tid < 64) {
        int p = tid & 31;
        int g = (tid < 32 ? tx0 : ty0) + p;
        float s = T[0];
        s += (g >= 1 ? T[1] : 0.f) + (g >= 2 ? T[2] : 0.f) + (g >= 3 ? T[3] : 0.f)
           + (g >= 4 ? T[4] : 0.f) + (g >= 5 ? T[5] : 0.f) + (g >= 6 ? T[6] : 0.f);
        int d = w - 1 - g;
        s += (d >= 1 ? T[1] : 0.f) + (d >= 2 ? T[2] : 0.f) + (d >= 3 ? T[3] : 0.f)
           + (d >= 4 ? T[4] : 0.f) + (d >= 5 ? T[5] : 0.f) + (d >= 6 ? T[6] : 0.f);
        if (tid < 32) s_sx[p] = s; else s_sy[p] = s;
    }

    // ---- phase 1: luminance gather (incremental indexing; no div in loop) ----
    {
        int r = tid / 44;
        int c = tid - r * 44;
        const bool interior = (tx0 >= HALO) && (ty0 >= HALO) &&
                              (tx0 + TS + HALO <= w) && (ty0 + TS + HALO <= h);
        float* slin = &s_lum[0][0];
        if (interior) {
            int goff = ((ty0 - HALO + r) * w + (tx0 - HALO + c)) * 3;
            const int dA = (5 * w + 36) * 3;
            const int dB = (6 * w - 8) * 3;
            int idx = tid;
#pragma unroll
            for (int it = 0; it < 7; it++) {
                const float* p = base + goff;
                slin[idx] = 0.2989f * p[0] + 0.587f * p[1] + 0.114f * p[2];
                idx += 256;
                int cn = c + 36;
                bool wrap = cn >= 44;
                c = wrap ? cn - 44 : cn;
                goff += wrap ? dB : dA;
            }
            if (idx < LW * LW) {
                const float* p = base + goff;
                slin[idx] = 0.2989f * p[0] + 0.587f * p[1] + 0.114f * p[2];
            }
        } else {
            int idx = tid;
#pragma unroll
            for (int it = 0; it < 8; it++) {
                if (idx < LW * LW) {
                    int gy = ty0 - HALO + r;
                    int gx = tx0 - HALO + c;
                    float v = 0.0f;
                    if ((unsigned)gy < (unsigned)h && (unsigned)gx < (unsigned)w) {
                        const float* p = base + (gy * w + gx) * 3;
                        v = 0.2989f * p[0] + 0.587f * p[1] + 0.114f * p[2];
                    }
                    slin[idx] = v;
                }
                idx += 256;
                int cn = c + 36;
                bool wrap = cn >= 44;
                c = wrap ? cn - 44 : cn;
                r += wrap ? 6 : 5;
            }
        }
    }
    __syncthreads();

    // ---- phase 2: horizontal 13-tap blur, 4 outputs/thread, streaming accs ----
    // contribution of element m (0..15) to output j: tap T[|m-6-j|], valid if <=6
#define CONTRIB2(vv, m)                                             \
    { if ((m) <= 12)              o0 += T[(m) >= 6 ? (m)-6 : 6-(m)] * (vv); \
      if ((m) >= 1 && (m) <= 13)  o1 += T[(m) >= 7 ? (m)-7 : 7-(m)] * (vv); \
      if ((m) >= 2 && (m) <= 14)  o2 += T[(m) >= 8 ? (m)-8 : 8-(m)] * (vv); \
      if ((m) >= 3)               o3 += T[(m) >= 9 ? (m)-9 : 9-(m)] * (vv); }

    {
        int t = tid;
#pragma unroll
        for (int pass = 0; pass < 2; pass++) {
            if (t < LW * 8) {
                int r  = t >> 3;
                int cg = (t & 7) << 2;
                const float* row = &s_lum[r][cg];
                float o0 = 0.f, o1 = 0.f, o2 = 0.f, o3 = 0.f;
#pragma unroll
                for (int g = 0; g < 4; g++) {
                    float4 q = *(const float4*)(row + 4 * g);
                    CONTRIB2(q.x, 4 * g + 0);
                    CONTRIB2(q.y, 4 * g + 1);
                    CONTRIB2(q.z, 4 * g + 2);
                    CONTRIB2(q.w, 4 * g + 3);
                }
                *(float4*)&s_h[r][cg] = make_float4(o0, o1, o2, o3);
            }
            t += 256;
        }
    }
    __syncthreads();

    // ---- phase 3a: vertical blur (4 rows/thread), dens, inv -> smem ----
    {
        const int c  = tid & 31;
        const int r0 = (tid >> 5) << 2;
        float o0 = 0.f, o1 = 0.f, o2 = 0.f, o3 = 0.f;
        const float* colp = &s_h[r0][c];
#pragma unroll
        for (int m = 0; m < 16; m++) {
            float vv = colp[m * TS];
            CONTRIB2(vv, m);
        }
        const float sx = s_sx[c];
        {
            float dens = 0.9999f * s_sy[r0 + 0] * sx;
            s_inv[r0 + 0][c] = __fdividef(dens, o0 + 1e-3f * dens);
        }
        {
            float dens = 0.9999f * s_sy[r0 + 1] * sx;
            s_inv[r0 + 1][c] = __fdividef(dens, o1 + 1e-3f * dens);
        }
        {
            float dens = 0.9999f * s_sy[r0 + 2] * sx;
            s_inv[r0 + 2][c] = __fdividef(dens, o2 + 1e-3f * dens);
        }
        {
            float dens = 0.9999f * s_sy[r0 + 3] * sx;
            s_inv[r0 + 3][c] = __fdividef(dens, o3 + 1e-3f * dens);
        }
    }
    __syncthreads();

    // ---- phase 3b: vectorized I/O. Tile row = 96 floats = 24 float4, 16B aligned.
    // 32 rows * 24 float4 = 768 tasks, 3 per thread.
    {
        int t = tid;
#pragma unroll
        for (int it = 0; it < 3; it++) {
            int row = t / 24;
            int f   = t - row * 24;
            int u   = f << 2;           // first float element in row (0..92)
            int p0  = (u * 0x5556) >> 16;   // u/3 for u<96
            int fm3 = u - 3 * p0;           // == f % 3
            int th  = 3 - fm3;

            float iA = s_inv[row][p0];
            float iB = s_inv[row][p0 + 1 < 32 ? p0 + 1 : 31];  // p0+1 only used when valid

            int goff = ((ty0 + row) * w + tx0) * 3 + u;
            float4 q = *(const float4*)(base + goff);
            q.x *= iA;                       // k=0 < th always
            q.y *= (1 < th) ? iA : iB;
            q.z *= (2 < th) ? iA : iB;
            q.w *= iB;                       // k=3 >= th always
            *(float4*)(obase + goff) = q;
            t += 256;
        }
    }
}

extern "C" void kernel_launch(void* const* d_in, const int* in_sizes, int n_in,
                              void* d_out, int out_size)
{
    const float* x = (const float*)d_in[0];
    float* out     = (float*)d_out;
    dim3 grid(85, 128);
    lln_kernel<<<grid, 256>>>(x, out);
}